// round 1
// baseline (speedup 1.0000x reference)
#include <cuda_runtime.h>
#include <cuda_bf16.h>
#include <math.h>

// Problem constants
#define T_TOK 2048
#define D_MODEL 3584
#define HQ 28
#define HKV 4
#define DH 128
#define QKV_OUT ((HQ + 2*HKV) * DH)   // 4608
#define ATTN_DIM (HQ * DH)            // 3584
#define GQA_G (HQ / HKV)              // 7
#define SM_SCALE 0.08838834764831845f // 1/sqrt(128)

// Scratch (static device allocations are allowed)
__device__ float g_qkv[T_TOK * QKV_OUT];    // 2048 x 4608
__device__ float g_attn[T_TOK * ATTN_DIM];  // 2048 x 3584
__device__ float g_rope_cos[T_TOK * (DH/2)];
__device__ float g_rope_sin[T_TOK * (DH/2)];

// ---------------------------------------------------------------------------
// Tiled fp32 SGEMM: C[M,N] = A[M,K] @ B[K,N] (+ bias[N])
// BM=BN=128, BK=16, TM=TN=8, 256 threads. All dims divisible (no guards).
// ---------------------------------------------------------------------------
template<bool HAS_BIAS>
__global__ __launch_bounds__(256) void sgemm128(
    const float* __restrict__ A, const float* __restrict__ B,
    const float* __restrict__ bias, float* __restrict__ C,
    int M, int N, int K)
{
    const int BM = 128, BN = 128, BK = 16, TM = 8, TN = 8;
    __shared__ float As[BK][BM + 4];   // A stored transposed [k][m], padded
    __shared__ float Bs[BK][BN];       // natural [k][n]

    const int tid = threadIdx.x;
    const int bx = blockIdx.x, by = blockIdx.y;
    const int tr = tid / 16, tc = tid % 16;

    const int rowA = tid >> 2;            // 0..63 (+64 on second pass)
    const int colA = (tid & 3) * 4;       // 0,4,8,12
    const int rowB = tid >> 5;            // 0..7  (+8 on second pass)
    const int colB = (tid & 31) * 4;      // 0..124

    const float* Ab = A + (size_t)by * BM * K;
    const float* Bb = B + (size_t)bx * BN;

    float acc[TM][TN];
    #pragma unroll
    for (int i = 0; i < TM; i++)
        #pragma unroll
        for (int j = 0; j < TN; j++) acc[i][j] = 0.0f;

    for (int bk = 0; bk < K; bk += BK) {
        // Load A tile (transposed into As)
        #pragma unroll
        for (int t = 0; t < 2; t++) {
            int r = rowA + t * 64;
            float4 a = *(const float4*)(Ab + (size_t)r * K + bk + colA);
            As[colA + 0][r] = a.x;
            As[colA + 1][r] = a.y;
            As[colA + 2][r] = a.z;
            As[colA + 3][r] = a.w;
        }
        // Load B tile
        #pragma unroll
        for (int t = 0; t < 2; t++) {
            int r = rowB + t * 8;
            *(float4*)(&Bs[r][colB]) =
                *(const float4*)(Bb + (size_t)(bk + r) * N + colB);
        }
        __syncthreads();

        #pragma unroll
        for (int k = 0; k < BK; k++) {
            float regM[TM], regN[TN];
            *(float4*)(regM)     = *(const float4*)(&As[k][tr * TM]);
            *(float4*)(regM + 4) = *(const float4*)(&As[k][tr * TM + 4]);
            *(float4*)(regN)     = *(const float4*)(&Bs[k][tc * TN]);
            *(float4*)(regN + 4) = *(const float4*)(&Bs[k][tc * TN + 4]);
            #pragma unroll
            for (int i = 0; i < TM; i++)
                #pragma unroll
                for (int j = 0; j < TN; j++)
                    acc[i][j] = fmaf(regM[i], regN[j], acc[i][j]);
        }
        __syncthreads();
    }

    // Epilogue
    #pragma unroll
    for (int i = 0; i < TM; i++) {
        int row = by * BM + tr * TM + i;
        #pragma unroll
        for (int j = 0; j < TN; j += 4) {
            int col = bx * BN + tc * TN + j;
            float4 v;
            v.x = acc[i][j + 0];
            v.y = acc[i][j + 1];
            v.z = acc[i][j + 2];
            v.w = acc[i][j + 3];
            if (HAS_BIAS) {
                v.x += bias[col + 0];
                v.y += bias[col + 1];
                v.z += bias[col + 2];
                v.w += bias[col + 3];
            }
            *(float4*)(C + (size_t)row * N + col) = v;
        }
    }
}

// ---------------------------------------------------------------------------
// RoPE cos/sin table (double precision for angle accuracy at pos up to 2047)
// ---------------------------------------------------------------------------
__global__ void rope_table_kernel(const int* __restrict__ positions)
{
    int idx = blockIdx.x * blockDim.x + threadIdx.x; // t*64 + i
    if (idx >= T_TOK * (DH/2)) return;
    int t = idx >> 6;
    int i = idx & 63;
    double inv = pow(1.0e6, -(double)i / 64.0);
    double ang = (double)positions[t] * inv;
    g_rope_cos[idx] = (float)cos(ang);
    g_rope_sin[idx] = (float)sin(ang);
}

// Apply RoPE in-place to Q heads (0..27) and K heads (28..31) of g_qkv
__global__ void rope_apply_kernel(float* __restrict__ qkv)
{
    int t = blockIdx.x;
    int head = blockIdx.y * blockDim.y + threadIdx.y;  // 0..31
    int i = threadIdx.x;                               // 0..63
    float c = g_rope_cos[t * 64 + i];
    float s = g_rope_sin[t * 64 + i];
    size_t base = (size_t)t * QKV_OUT + head * DH;
    float x1 = qkv[base + i];
    float x2 = qkv[base + 64 + i];
    qkv[base + i]      = x1 * c - x2 * s;
    qkv[base + 64 + i] = x2 * c + x1 * s;
}

// ---------------------------------------------------------------------------
// Flash-attention (fp32, causal, GQA). BQ=128, BKV=64, 256 threads.
// Thread (tr,tc): tr=tid/16 (row group of 8), tc=tid%16.
//  - S phase: thread computes s[8][4]  (rows tr*8+i, keys tc*4+j)
//  - PV phase: thread computes o[8][8] (rows tr*8+i, dims tc*8+j)
// Smem: QT[d][r] (d-major), KT[d][c] (d-major), Vs[c][d], Ps[r][c]
// ---------------------------------------------------------------------------
#define RLQ 132
#define RLK 68
#define RLV 132
#define RLP 68
#define ATT_SMEM_FLOATS (128*RLQ + 128*RLK + 64*RLV + 128*RLP)

__global__ __launch_bounds__(256, 1) void attn_kernel(
    const float* __restrict__ qkv, float* __restrict__ out)
{
    extern __shared__ float sm[];
    float* QT = sm;                     // [128][RLQ]
    float* KT = QT + 128 * RLQ;         // [128][RLK]
    float* Vs = KT + 128 * RLK;         // [64][RLV]
    float* Ps = Vs + 64 * RLV;          // [128][RLP]

    const int qb = blockIdx.x;          // 0..15
    const int h  = blockIdx.y;          // 0..27
    const int kvh = h / GQA_G;
    const int tid = threadIdx.x;
    const int tr = tid / 16, tc = tid % 16;

    const int QOFF = h * DH;
    const int KOFF = (HQ + kvh) * DH;
    const int VOFF = (HQ + HKV + kvh) * DH;
    const int q0 = qb * 128;

    // Load Q block transposed: QT[d][r]
    for (int i = tid; i < 128 * 128; i += 256) {
        int r = i >> 7, d = i & 127;
        QT[d * RLQ + r] = qkv[(size_t)(q0 + r) * QKV_OUT + QOFF + d];
    }

    float o[8][8];
    float m[8], l[8];
    #pragma unroll
    for (int i = 0; i < 8; i++) {
        m[i] = -1e30f; l[i] = 0.0f;
        #pragma unroll
        for (int j = 0; j < 8; j++) o[i][j] = 0.0f;
    }
    __syncthreads();

    const int nkb = 2 * qb + 2;  // causal: key blocks 0 .. 2qb+1
    for (int kb = 0; kb < nkb; kb++) {
        __syncthreads();  // previous iteration's Ps/Vs readers done
        // Load K (transposed) and V for this 64-token block
        for (int i = tid; i < 64 * 128; i += 256) {
            int c = i >> 7, d = i & 127;
            size_t base = (size_t)(kb * 64 + c) * QKV_OUT;
            KT[d * RLK + c] = qkv[base + KOFF + d];
            Vs[c * RLV + d] = qkv[base + VOFF + d];
        }
        __syncthreads();

        // S = Q @ K^T  (thread: rows tr*8.., keys tc*4..)
        float s[8][4];
        #pragma unroll
        for (int i = 0; i < 8; i++)
            #pragma unroll
            for (int j = 0; j < 4; j++) s[i][j] = 0.0f;

        #pragma unroll 2
        for (int d = 0; d < 128; d++) {
            float qreg[8], kreg[4];
            *(float4*)(qreg)     = *(const float4*)(&QT[d * RLQ + tr * 8]);
            *(float4*)(qreg + 4) = *(const float4*)(&QT[d * RLQ + tr * 8 + 4]);
            *(float4*)(kreg)     = *(const float4*)(&KT[d * RLK + tc * 4]);
            #pragma unroll
            for (int i = 0; i < 8; i++)
                #pragma unroll
                for (int j = 0; j < 4; j++)
                    s[i][j] = fmaf(qreg[i], kreg[j], s[i][j]);
        }

        // Scale + causal mask (only partial blocks need masking)
        const bool partial = (kb >= 2 * qb);
        #pragma unroll
        for (int i = 0; i < 8; i++) {
            #pragma unroll
            for (int j = 0; j < 4; j++) {
                float v = s[i][j] * SM_SCALE;
                if (partial) {
                    int gq = q0 + tr * 8 + i;
                    int gk = kb * 64 + tc * 4 + j;
                    if (gk > gq) v = -1e9f;
                }
                s[i][j] = v;
            }
        }

        // Online softmax. Row owned by 16 lanes (tc); reduce via shfl_xor 1,2,4,8.
        #pragma unroll
        for (int i = 0; i < 8; i++) {
            float mx = fmaxf(fmaxf(s[i][0], s[i][1]), fmaxf(s[i][2], s[i][3]));
            #pragma unroll
            for (int off = 1; off < 16; off <<= 1)
                mx = fmaxf(mx, __shfl_xor_sync(0xffffffffu, mx, off));
            float mnew = fmaxf(m[i], mx);
            float alpha = __expf(m[i] - mnew);
            m[i] = mnew;

            float rs = 0.0f;
            #pragma unroll
            for (int j = 0; j < 4; j++) {
                s[i][j] = __expf(s[i][j] - mnew);
                rs += s[i][j];
            }
            #pragma unroll
            for (int off = 1; off < 16; off <<= 1)
                rs += __shfl_xor_sync(0xffffffffu, rs, off);
            l[i] = l[i] * alpha + rs;
            #pragma unroll
            for (int j = 0; j < 8; j++) o[i][j] *= alpha;
        }

        // Publish P to smem
        #pragma unroll
        for (int i = 0; i < 8; i++)
            #pragma unroll
            for (int j = 0; j < 4; j++)
                Ps[(tr * 8 + i) * RLP + tc * 4 + j] = s[i][j];
        __syncthreads();

        // o += P @ V  (thread: rows tr*8.., dims tc*8..)
        #pragma unroll 2
        for (int c = 0; c < 64; c++) {
            float p[8], v[8];
            #pragma unroll
            for (int i = 0; i < 8; i++)
                p[i] = Ps[(tr * 8 + i) * RLP + c];
            *(float4*)(v)     = *(const float4*)(&Vs[c * RLV + tc * 8]);
            *(float4*)(v + 4) = *(const float4*)(&Vs[c * RLV + tc * 8 + 4]);
            #pragma unroll
            for (int i = 0; i < 8; i++)
                #pragma unroll
                for (int j = 0; j < 8; j++)
                    o[i][j] = fmaf(p[i], v[j], o[i][j]);
        }
    }

    // Epilogue: normalize and write attn output [T, HQ*DH]
    #pragma unroll
    for (int i = 0; i < 8; i++) {
        float inv = 1.0f / l[i];
        int row = q0 + tr * 8 + i;
        float4 v0, v1;
        v0.x = o[i][0] * inv; v0.y = o[i][1] * inv;
        v0.z = o[i][2] * inv; v0.w = o[i][3] * inv;
        v1.x = o[i][4] * inv; v1.y = o[i][5] * inv;
        v1.z = o[i][6] * inv; v1.w = o[i][7] * inv;
        size_t base = (size_t)row * ATTN_DIM + h * DH + tc * 8;
        *(float4*)(out + base)     = v0;
        *(float4*)(out + base + 4) = v1;
    }
}

// ---------------------------------------------------------------------------
// Launch
// ---------------------------------------------------------------------------
extern "C" void kernel_launch(void* const* d_in, const int* in_sizes, int n_in,
                              void* d_out, int out_size)
{
    const int*   positions = (const int*)  d_in[0];
    const float* hidden    = (const float*)d_in[1];
    const float* W_qkv     = (const float*)d_in[2];
    const float* b_qkv     = (const float*)d_in[3];
    const float* W_o       = (const float*)d_in[4];
    float* out = (float*)d_out;

    float* qkv;  cudaGetSymbolAddress((void**)&qkv,  g_qkv);
    float* attn; cudaGetSymbolAddress((void**)&attn, g_attn);

    // Opt-in to large dynamic smem for the attention kernel (idempotent)
    cudaFuncSetAttribute(attn_kernel,
                         cudaFuncAttributeMaxDynamicSharedMemorySize,
                         ATT_SMEM_FLOATS * (int)sizeof(float));

    // 1) QKV projection: [2048,3584] @ [3584,4608] + bias
    {
        dim3 grid(QKV_OUT / 128, T_TOK / 128);
        sgemm128<true><<<grid, 256>>>(hidden, W_qkv, b_qkv, qkv,
                                      T_TOK, QKV_OUT, D_MODEL);
    }

    // 2) RoPE table + apply
    {
        int n = T_TOK * (DH / 2);
        rope_table_kernel<<<(n + 255) / 256, 256>>>(positions);
        dim3 grid(T_TOK, (HQ + HKV) / 4);
        dim3 block(64, 4);
        rope_apply_kernel<<<grid, block>>>(qkv);
    }

    // 3) Causal GQA flash attention
    {
        dim3 grid(T_TOK / 128, HQ);
        attn_kernel<<<grid, 256, ATT_SMEM_FLOATS * sizeof(float)>>>(qkv, attn);
    }

    // 4) Output projection: [2048,3584] @ [3584,3584]
    {
        dim3 grid(D_MODEL / 128, T_TOK / 128);
        sgemm128<false><<<grid, 256>>>(attn, W_o, nullptr, out,
                                       T_TOK, D_MODEL, ATTN_DIM);
    }
}

// round 4
// speedup vs baseline: 1.6705x; 1.6705x over previous
#include <cuda_runtime.h>
#include <cuda_bf16.h>
#include <math.h>
#include <cstdint>

// ---------------------------------------------------------------------------
// Problem constants
// ---------------------------------------------------------------------------
#define T_TOK 2048
#define D_MODEL 3584
#define HQ 28
#define HKV 4
#define DH 128
#define QKV_OUT ((HQ + 2*HKV) * DH)   // 4608
#define ATTN_DIM (HQ * DH)            // 3584
#define GQA_G (HQ / HKV)              // 7
#define SM_SCALE 0.08838834764831845f // 1/sqrt(128)

// ---------------------------------------------------------------------------
// Scratch (static device allocations are allowed)
// ---------------------------------------------------------------------------
__device__ float g_qkv[T_TOK * QKV_OUT];    // 2048 x 4608 fp32
__device__ float g_attn[T_TOK * ATTN_DIM];  // 2048 x 3584 fp32
__device__ float g_rope_cos[T_TOK * (DH/2)];
__device__ float g_rope_sin[T_TOK * (DH/2)];

// bf16 split operands
__device__ __nv_bfloat16 g_X_hi[T_TOK * D_MODEL];      // hidden, [M][K]
__device__ __nv_bfloat16 g_X_lo[T_TOK * D_MODEL];
__device__ __nv_bfloat16 g_A_hi[T_TOK * ATTN_DIM];     // attn out, [M][K]
__device__ __nv_bfloat16 g_A_lo[T_TOK * ATTN_DIM];
__device__ __nv_bfloat16 g_Wq_hi[QKV_OUT * D_MODEL];   // W_qkv^T, [N][K]
__device__ __nv_bfloat16 g_Wq_lo[QKV_OUT * D_MODEL];
__device__ __nv_bfloat16 g_Wo_hi[D_MODEL * ATTN_DIM];  // W_o^T, [N][K]
__device__ __nv_bfloat16 g_Wo_lo[D_MODEL * ATTN_DIM];

// ---------------------------------------------------------------------------
// Helpers
// ---------------------------------------------------------------------------
__device__ __forceinline__ uint32_t smem_u32(const void* p) {
    uint32_t a;
    asm("{ .reg .u64 t; cvta.to.shared.u64 t, %1; cvt.u32.u64 %0, t; }"
        : "=r"(a) : "l"(p));
    return a;
}

__device__ __forceinline__ uint32_t lds_u32(uint32_t a) {
    uint32_t v;
    asm volatile("ld.shared.b32 %0, [%1];" : "=r"(v) : "r"(a));
    return v;
}

#define CP_ASYNC16(saddr, gptr) \
    asm volatile("cp.async.cg.shared.global [%0], [%1], 16;" \
                 :: "r"(saddr), "l"(gptr))
#define CP_COMMIT() asm volatile("cp.async.commit_group;" ::: "memory")
#define CP_WAIT(n)  asm volatile("cp.async.wait_group %0;" :: "n"(n) : "memory")

__device__ __forceinline__ void mma_bf16(float* c, const uint32_t* a,
                                         const uint32_t* b) {
    asm volatile(
        "mma.sync.aligned.m16n8k16.row.col.f32.bf16.bf16.f32 "
        "{%0,%1,%2,%3}, {%4,%5,%6,%7}, {%8,%9}, {%0,%1,%2,%3};"
        : "+f"(c[0]), "+f"(c[1]), "+f"(c[2]), "+f"(c[3])
        : "r"(a[0]), "r"(a[1]), "r"(a[2]), "r"(a[3]),
          "r"(b[0]), "r"(b[1]));
}

// ---------------------------------------------------------------------------
// Prep kernels: fp32 -> bf16 hi/lo split (row-major), and transpose+split
// ---------------------------------------------------------------------------
__global__ void convert_split_kernel(const float* __restrict__ in,
                                     __nv_bfloat16* __restrict__ hi,
                                     __nv_bfloat16* __restrict__ lo, int n2)
{
    int i = blockIdx.x * blockDim.x + threadIdx.x;
    if (i >= n2) return;
    float2 v = ((const float2*)in)[i];
    __nv_bfloat16 h0 = __float2bfloat16(v.x);
    __nv_bfloat16 h1 = __float2bfloat16(v.y);
    __nv_bfloat162 hh; hh.x = h0; hh.y = h1;
    __nv_bfloat162 ll;
    ll.x = __float2bfloat16(v.x - __bfloat162float(h0));
    ll.y = __float2bfloat16(v.y - __bfloat162float(h1));
    ((__nv_bfloat162*)hi)[i] = hh;
    ((__nv_bfloat162*)lo)[i] = ll;
}

// in [R][C] fp32 -> out [C][R] bf16 hi/lo
__global__ void transpose_split_kernel(const float* __restrict__ in,
                                       __nv_bfloat16* __restrict__ hi,
                                       __nv_bfloat16* __restrict__ lo,
                                       int R, int C)
{
    __shared__ float t[32][33];
    int c0 = blockIdx.x * 32, r0 = blockIdx.y * 32;
    int tx = threadIdx.x, ty = threadIdx.y;
    #pragma unroll
    for (int j = ty; j < 32; j += 8)
        t[j][tx] = in[(size_t)(r0 + j) * C + c0 + tx];
    __syncthreads();
    #pragma unroll
    for (int j = ty; j < 32; j += 8) {
        float v = t[tx][j];  // in[r0+tx][c0+j]
        __nv_bfloat16 h = __float2bfloat16(v);
        size_t o = (size_t)(c0 + j) * R + r0 + tx;
        hi[o] = h;
        lo[o] = __float2bfloat16(v - __bfloat162float(h));
    }
}

// ---------------------------------------------------------------------------
// mma.sync bf16x3 GEMM: C[M,N] = A[M,K] @ B[N,K]^T (+bias), fp32 out
// Block 128x128, BK=32, 8 warps (each 32M x 64N), cp.async double buffer.
// Smem stage layout (pitch 80B = 40 bf16 per 32-col row):
//   sAhi [128][40] @ +0      sAlo @ +10240
//   sBhi [128][40] @ +20480  sBlo @ +30720
// ---------------------------------------------------------------------------
#define GSTAGE 40960
#define GEMM_SMEM (2 * GSTAGE)

__global__ __launch_bounds__(256, 1) void gemm_mma_bf16x3(
    const __nv_bfloat16* __restrict__ Ahi, const __nv_bfloat16* __restrict__ Alo,
    const __nv_bfloat16* __restrict__ Bhi, const __nv_bfloat16* __restrict__ Blo,
    const float* __restrict__ bias, float* __restrict__ C,
    int M, int N, int K)
{
    extern __shared__ char dsm[];
    const int tid  = threadIdx.x;
    const int lane = tid & 31, wid = tid >> 5;
    const int wm = wid & 3;          // 0..3 -> M offset wm*32
    const int wn = wid >> 2;         // 0..1 -> N offset wn*64
    const int g  = lane >> 2, t = lane & 3;
    const int m0 = blockIdx.y * 128, n0 = blockIdx.x * 128;

    const uint32_t sbase = smem_u32(dsm);

    float acc[2][8][4];
    #pragma unroll
    for (int mt = 0; mt < 2; mt++)
        #pragma unroll
        for (int nt = 0; nt < 8; nt++)
            #pragma unroll
            for (int j = 0; j < 4; j++) acc[mt][nt][j] = 0.0f;

    const int niter = K / 32;

    // Per-thread load mapping: 512 16B-chunks per matrix per stage
    const int lrow0 = tid >> 1;          // c = tid: row=tid>>2... use loop form

    // ---- stage loader ----
    #define LOAD_STAGE(it) do {                                               \
        int _st = (it) & 1; int _kb = (it) * 32;                              \
        uint32_t _s0 = sbase + _st * GSTAGE;                                  \
        _Pragma("unroll")                                                     \
        for (int _c = tid; _c < 512; _c += 256) {                             \
            int _row = _c >> 2, _c8 = _c & 3;                                 \
            uint32_t _so = (uint32_t)(_row * 80 + _c8 * 16);                  \
            size_t _ga = (size_t)(m0 + _row) * K + _kb + _c8 * 8;             \
            size_t _gb = (size_t)(n0 + _row) * K + _kb + _c8 * 8;             \
            CP_ASYNC16(_s0 + _so,          Ahi + _ga);                        \
            CP_ASYNC16(_s0 + 10240 + _so,  Alo + _ga);                        \
            CP_ASYNC16(_s0 + 20480 + _so,  Bhi + _gb);                        \
            CP_ASYNC16(_s0 + 30720 + _so,  Blo + _gb);                        \
        }                                                                     \
        CP_COMMIT();                                                          \
    } while (0)

    LOAD_STAGE(0);

    for (int it = 0; it < niter; it++) {
        if (it + 1 < niter) {
            LOAD_STAGE(it + 1);
            CP_WAIT(1);
        } else {
            CP_WAIT(0);
        }
        __syncthreads();

        const uint32_t s0 = sbase + (it & 1) * GSTAGE;
        #pragma unroll
        for (int ks = 0; ks < 2; ks++) {
            const uint32_t koff = (uint32_t)(ks * 32 + t * 4);
            const uint32_t aB = s0 + (uint32_t)((wm * 32 + g) * 80) + koff;
            const uint32_t bB = s0 + 20480u + (uint32_t)((wn * 64 + g) * 80) + koff;

            uint32_t a[2][4], bhi[8][2], blo[8][2];

            // A-hi fragments (2 m-tiles)
            #pragma unroll
            for (int mt = 0; mt < 2; mt++) {
                uint32_t ab = aB + (uint32_t)(mt * 16 * 80);
                a[mt][0] = lds_u32(ab);
                a[mt][1] = lds_u32(ab + 640);
                a[mt][2] = lds_u32(ab + 16);
                a[mt][3] = lds_u32(ab + 656);
            }
            // B-hi fragments (8 n-tiles)
            #pragma unroll
            for (int nt = 0; nt < 8; nt++) {
                uint32_t bb = bB + (uint32_t)(nt * 8 * 80);
                bhi[nt][0] = lds_u32(bb);
                bhi[nt][1] = lds_u32(bb + 16);
            }
            // pass 1: Ahi * Bhi
            #pragma unroll
            for (int mt = 0; mt < 2; mt++)
                #pragma unroll
                for (int nt = 0; nt < 8; nt++)
                    mma_bf16(acc[mt][nt], a[mt], bhi[nt]);

            // B-lo fragments
            #pragma unroll
            for (int nt = 0; nt < 8; nt++) {
                uint32_t bb = bB + 10240u + (uint32_t)(nt * 8 * 80);
                blo[nt][0] = lds_u32(bb);
                blo[nt][1] = lds_u32(bb + 16);
            }
            // pass 2: Ahi * Blo
            #pragma unroll
            for (int mt = 0; mt < 2; mt++)
                #pragma unroll
                for (int nt = 0; nt < 8; nt++)
                    mma_bf16(acc[mt][nt], a[mt], blo[nt]);

            // A-lo fragments (overwrite a)
            #pragma unroll
            for (int mt = 0; mt < 2; mt++) {
                uint32_t ab = aB + 10240u + (uint32_t)(mt * 16 * 80);
                a[mt][0] = lds_u32(ab);
                a[mt][1] = lds_u32(ab + 640);
                a[mt][2] = lds_u32(ab + 16);
                a[mt][3] = lds_u32(ab + 656);
            }
            // pass 3: Alo * Bhi
            #pragma unroll
            for (int mt = 0; mt < 2; mt++)
                #pragma unroll
                for (int nt = 0; nt < 8; nt++)
                    mma_bf16(acc[mt][nt], a[mt], bhi[nt]);
        }
        __syncthreads();
    }

    // Epilogue: write C (+bias)
    const bool hasb = (bias != nullptr);
    #pragma unroll
    for (int mt = 0; mt < 2; mt++) {
        int row0 = m0 + wm * 32 + mt * 16 + g;
        #pragma unroll
        for (int nt = 0; nt < 8; nt++) {
            int col = n0 + wn * 64 + nt * 8 + t * 2;
            float bx = hasb ? bias[col] : 0.0f;
            float by = hasb ? bias[col + 1] : 0.0f;
            float2 v0, v1;
            v0.x = acc[mt][nt][0] + bx; v0.y = acc[mt][nt][1] + by;
            v1.x = acc[mt][nt][2] + bx; v1.y = acc[mt][nt][3] + by;
            *(float2*)(C + (size_t)row0 * N + col) = v0;
            *(float2*)(C + (size_t)(row0 + 8) * N + col) = v1;
        }
    }
    #undef LOAD_STAGE
}

// ---------------------------------------------------------------------------
// RoPE
// ---------------------------------------------------------------------------
__global__ void rope_table_kernel(const int* __restrict__ positions)
{
    int idx = blockIdx.x * blockDim.x + threadIdx.x;
    if (idx >= T_TOK * (DH/2)) return;
    int t = idx >> 6;
    int i = idx & 63;
    double inv = pow(1.0e6, -(double)i / 64.0);
    double ang = (double)positions[t] * inv;
    g_rope_cos[idx] = (float)cos(ang);
    g_rope_sin[idx] = (float)sin(ang);
}

__global__ void rope_apply_kernel(float* __restrict__ qkv)
{
    int t = blockIdx.x;
    int head = blockIdx.y * blockDim.y + threadIdx.y;  // 0..31
    int i = threadIdx.x;                               // 0..63
    float c = g_rope_cos[t * 64 + i];
    float s = g_rope_sin[t * 64 + i];
    size_t base = (size_t)t * QKV_OUT + head * DH;
    float x1 = qkv[base + i];
    float x2 = qkv[base + 64 + i];
    qkv[base + i]      = x1 * c - x2 * s;
    qkv[base + 64 + i] = x2 * c + x1 * s;
}

// ---------------------------------------------------------------------------
// Flash attention (fp32, causal, GQA) — unchanged
// ---------------------------------------------------------------------------
#define RLQ 132
#define RLK 68
#define RLV 132
#define RLP 68
#define ATT_SMEM_FLOATS (128*RLQ + 128*RLK + 64*RLV + 128*RLP)

__global__ __launch_bounds__(256, 1) void attn_kernel(
    const float* __restrict__ qkv, float* __restrict__ out)
{
    extern __shared__ float sm[];
    float* QT = sm;
    float* KT = QT + 128 * RLQ;
    float* Vs = KT + 128 * RLK;
    float* Ps = Vs + 64 * RLV;

    const int qb = blockIdx.x;
    const int h  = blockIdx.y;
    const int kvh = h / GQA_G;
    const int tid = threadIdx.x;
    const int tr = tid / 16, tc = tid % 16;

    const int QOFF = h * DH;
    const int KOFF = (HQ + kvh) * DH;
    const int VOFF = (HQ + HKV + kvh) * DH;
    const int q0 = qb * 128;

    for (int i = tid; i < 128 * 128; i += 256) {
        int r = i >> 7, d = i & 127;
        QT[d * RLQ + r] = qkv[(size_t)(q0 + r) * QKV_OUT + QOFF + d];
    }

    float o[8][8];
    float m[8], l[8];
    #pragma unroll
    for (int i = 0; i < 8; i++) {
        m[i] = -1e30f; l[i] = 0.0f;
        #pragma unroll
        for (int j = 0; j < 8; j++) o[i][j] = 0.0f;
    }
    __syncthreads();

    const int nkb = 2 * qb + 2;
    for (int kb = 0; kb < nkb; kb++) {
        __syncthreads();
        for (int i = tid; i < 64 * 128; i += 256) {
            int c = i >> 7, d = i & 127;
            size_t base = (size_t)(kb * 64 + c) * QKV_OUT;
            KT[d * RLK + c] = qkv[base + KOFF + d];
            Vs[c * RLV + d] = qkv[base + VOFF + d];
        }
        __syncthreads();

        float s[8][4];
        #pragma unroll
        for (int i = 0; i < 8; i++)
            #pragma unroll
            for (int j = 0; j < 4; j++) s[i][j] = 0.0f;

        #pragma unroll 2
        for (int d = 0; d < 128; d++) {
            float qreg[8], kreg[4];
            *(float4*)(qreg)     = *(const float4*)(&QT[d * RLQ + tr * 8]);
            *(float4*)(qreg + 4) = *(const float4*)(&QT[d * RLQ + tr * 8 + 4]);
            *(float4*)(kreg)     = *(const float4*)(&KT[d * RLK + tc * 4]);
            #pragma unroll
            for (int i = 0; i < 8; i++)
                #pragma unroll
                for (int j = 0; j < 4; j++)
                    s[i][j] = fmaf(qreg[i], kreg[j], s[i][j]);
        }

        const bool partial = (kb >= 2 * qb);
        #pragma unroll
        for (int i = 0; i < 8; i++) {
            #pragma unroll
            for (int j = 0; j < 4; j++) {
                float v = s[i][j] * SM_SCALE;
                if (partial) {
                    int gq = q0 + tr * 8 + i;
                    int gk = kb * 64 + tc * 4 + j;
                    if (gk > gq) v = -1e9f;
                }
                s[i][j] = v;
            }
        }

        #pragma unroll
        for (int i = 0; i < 8; i++) {
            float mx = fmaxf(fmaxf(s[i][0], s[i][1]), fmaxf(s[i][2], s[i][3]));
            #pragma unroll
            for (int off = 1; off < 16; off <<= 1)
                mx = fmaxf(mx, __shfl_xor_sync(0xffffffffu, mx, off));
            float mnew = fmaxf(m[i], mx);
            float alpha = __expf(m[i] - mnew);
            m[i] = mnew;

            float rs = 0.0f;
            #pragma unroll
            for (int j = 0; j < 4; j++) {
                s[i][j] = __expf(s[i][j] - mnew);
                rs += s[i][j];
            }
            #pragma unroll
            for (int off = 1; off < 16; off <<= 1)
                rs += __shfl_xor_sync(0xffffffffu, rs, off);
            l[i] = l[i] * alpha + rs;
            #pragma unroll
            for (int j = 0; j < 8; j++) o[i][j] *= alpha;
        }

        #pragma unroll
        for (int i = 0; i < 8; i++)
            #pragma unroll
            for (int j = 0; j < 4; j++)
                Ps[(tr * 8 + i) * RLP + tc * 4 + j] = s[i][j];
        __syncthreads();

        #pragma unroll 2
        for (int c = 0; c < 64; c++) {
            float p[8], v[8];
            #pragma unroll
            for (int i = 0; i < 8; i++)
                p[i] = Ps[(tr * 8 + i) * RLP + c];
            *(float4*)(v)     = *(const float4*)(&Vs[c * RLV + tc * 8]);
            *(float4*)(v + 4) = *(const float4*)(&Vs[c * RLV + tc * 8 + 4]);
            #pragma unroll
            for (int i = 0; i < 8; i++)
                #pragma unroll
                for (int j = 0; j < 8; j++)
                    o[i][j] = fmaf(p[i], v[j], o[i][j]);
        }
    }

    #pragma unroll
    for (int i = 0; i < 8; i++) {
        float inv = 1.0f / l[i];
        int row = q0 + tr * 8 + i;
        float4 v0, v1;
        v0.x = o[i][0] * inv; v0.y = o[i][1] * inv;
        v0.z = o[i][2] * inv; v0.w = o[i][3] * inv;
        v1.x = o[i][4] * inv; v1.y = o[i][5] * inv;
        v1.z = o[i][6] * inv; v1.w = o[i][7] * inv;
        size_t base = (size_t)row * ATTN_DIM + h * DH + tc * 8;
        *(float4*)(out + base)     = v0;
        *(float4*)(out + base + 4) = v1;
    }
}

// ---------------------------------------------------------------------------
// Launch
// ---------------------------------------------------------------------------
extern "C" void kernel_launch(void* const* d_in, const int* in_sizes, int n_in,
                              void* d_out, int out_size)
{
    const int*   positions = (const int*)  d_in[0];
    const float* hidden    = (const float*)d_in[1];
    const float* W_qkv     = (const float*)d_in[2];
    const float* b_qkv     = (const float*)d_in[3];
    const float* W_o       = (const float*)d_in[4];
    float* out = (float*)d_out;

    float* qkv;  cudaGetSymbolAddress((void**)&qkv,  g_qkv);
    float* attn; cudaGetSymbolAddress((void**)&attn, g_attn);
    __nv_bfloat16 *Xhi, *Xlo, *Ahi, *Alo, *Wqh, *Wql, *Woh, *Wol;
    cudaGetSymbolAddress((void**)&Xhi, g_X_hi);
    cudaGetSymbolAddress((void**)&Xlo, g_X_lo);
    cudaGetSymbolAddress((void**)&Ahi, g_A_hi);
    cudaGetSymbolAddress((void**)&Alo, g_A_lo);
    cudaGetSymbolAddress((void**)&Wqh, g_Wq_hi);
    cudaGetSymbolAddress((void**)&Wql, g_Wq_lo);
    cudaGetSymbolAddress((void**)&Woh, g_Wo_hi);
    cudaGetSymbolAddress((void**)&Wol, g_Wo_lo);

    cudaFuncSetAttribute(attn_kernel,
                         cudaFuncAttributeMaxDynamicSharedMemorySize,
                         ATT_SMEM_FLOATS * (int)sizeof(float));
    cudaFuncSetAttribute(gemm_mma_bf16x3,
                         cudaFuncAttributeMaxDynamicSharedMemorySize,
                         GEMM_SMEM);

    // 0) Split inputs to bf16 hi/lo
    {
        int n2 = T_TOK * D_MODEL / 2;
        convert_split_kernel<<<(n2 + 255)/256, 256>>>(hidden, Xhi, Xlo, n2);
        dim3 g1(QKV_OUT/32, D_MODEL/32), b1(32, 8);
        transpose_split_kernel<<<g1, b1>>>(W_qkv, Wqh, Wql, D_MODEL, QKV_OUT);
        dim3 g2(D_MODEL/32, ATTN_DIM/32);
        transpose_split_kernel<<<g2, b1>>>(W_o, Woh, Wol, ATTN_DIM, D_MODEL);
    }

    // 1) QKV projection (mma.sync bf16x3): [2048,3584] @ [3584,4608] + bias
    {
        dim3 grid(QKV_OUT / 128, T_TOK / 128);   // 36 x 16
        gemm_mma_bf16x3<<<grid, 256, GEMM_SMEM>>>(
            Xhi, Xlo, Wqh, Wql, b_qkv, qkv, T_TOK, QKV_OUT, D_MODEL);
    }

    // 2) RoPE
    {
        int n = T_TOK * (DH / 2);
        rope_table_kernel<<<(n + 255) / 256, 256>>>(positions);
        dim3 grid(T_TOK, (HQ + HKV) / 4);
        dim3 block(64, 4);
        rope_apply_kernel<<<grid, block>>>(qkv);
    }

    // 3) Causal GQA flash attention (fp32)
    {
        dim3 grid(T_TOK / 128, HQ);
        attn_kernel<<<grid, 256, ATT_SMEM_FLOATS * sizeof(float)>>>(qkv, attn);
    }

    // 4) Split attention output, then O projection (mma.sync bf16x3)
    {
        int n2 = T_TOK * ATTN_DIM / 2;
        convert_split_kernel<<<(n2 + 255)/256, 256>>>(attn, Ahi, Alo, n2);
        dim3 grid(D_MODEL / 128, T_TOK / 128);   // 28 x 16
        gemm_mma_bf16x3<<<grid, 256, GEMM_SMEM>>>(
            Ahi, Alo, Woh, Wol, nullptr, out, T_TOK, D_MODEL, ATTN_DIM);
    }
}

// round 8
// speedup vs baseline: 2.4616x; 1.4736x over previous
#include <cuda_runtime.h>
#include <cuda_bf16.h>
#include <math.h>
#include <cstdint>

// ---------------------------------------------------------------------------
// Problem constants
// ---------------------------------------------------------------------------
#define T_TOK 2048
#define D_MODEL 3584
#define HQ 28
#define HKV 4
#define DH 128
#define QKV_OUT ((HQ + 2*HKV) * DH)   // 4608
#define ATTN_DIM (HQ * DH)            // 3584
#define GQA_G (HQ / HKV)              // 7
#define SM_SCALE 0.08838834764831845f // 1/sqrt(128)

// ---------------------------------------------------------------------------
// Scratch
// ---------------------------------------------------------------------------
__device__ float g_qkv[T_TOK * QKV_OUT];    // 2048 x 4608 fp32 (pre-rope)
__device__ float g_rope_cos[T_TOK * (DH/2)];
__device__ float g_rope_sin[T_TOK * (DH/2)];

// bf16 split operands for projections
__device__ __nv_bfloat16 g_X_hi[T_TOK * D_MODEL];      // hidden, [M][K]
__device__ __nv_bfloat16 g_X_lo[T_TOK * D_MODEL];
__device__ __nv_bfloat16 g_A_hi[T_TOK * ATTN_DIM];     // attn out, [M][K]
__device__ __nv_bfloat16 g_A_lo[T_TOK * ATTN_DIM];
__device__ __nv_bfloat16 g_Wq_hi[QKV_OUT * D_MODEL];   // W_qkv^T, [N][K]
__device__ __nv_bfloat16 g_Wq_lo[QKV_OUT * D_MODEL];
__device__ __nv_bfloat16 g_Wo_hi[D_MODEL * ATTN_DIM];  // W_o^T, [N][K]
__device__ __nv_bfloat16 g_Wo_lo[D_MODEL * ATTN_DIM];

// attention operands (post-rope, split)
__device__ __nv_bfloat16 g_Qhi[HQ * T_TOK * DH];   // [h][t][d]
__device__ __nv_bfloat16 g_Qlo[HQ * T_TOK * DH];
__device__ __nv_bfloat16 g_Khi[HKV * T_TOK * DH];  // [h][t][d]
__device__ __nv_bfloat16 g_Klo[HKV * T_TOK * DH];
__device__ __nv_bfloat16 g_Vthi[HKV * DH * T_TOK]; // [h][d][t] (transposed)
__device__ __nv_bfloat16 g_Vtlo[HKV * DH * T_TOK];

// ---------------------------------------------------------------------------
// Helpers
// ---------------------------------------------------------------------------
__device__ __forceinline__ uint32_t smem_u32(const void* p) {
    uint32_t a;
    asm("{ .reg .u64 t; cvta.to.shared.u64 t, %1; cvt.u32.u64 %0, t; }"
        : "=r"(a) : "l"(p));
    return a;
}

__device__ __forceinline__ uint32_t lds_u32(uint32_t a) {
    uint32_t v;
    asm volatile("ld.shared.b32 %0, [%1];" : "=r"(v) : "r"(a));
    return v;
}

#define CP_ASYNC16(saddr, gptr) \
    asm volatile("cp.async.cg.shared.global [%0], [%1], 16;" \
                 :: "r"(saddr), "l"(gptr))
#define CP_COMMIT() asm volatile("cp.async.commit_group;" ::: "memory")
#define CP_WAIT(n)  asm volatile("cp.async.wait_group %0;" :: "n"(n) : "memory")

__device__ __forceinline__ void mma_bf16(float* c, const uint32_t* a,
                                         const uint32_t* b) {
    asm volatile(
        "mma.sync.aligned.m16n8k16.row.col.f32.bf16.bf16.f32 "
        "{%0,%1,%2,%3}, {%4,%5,%6,%7}, {%8,%9}, {%0,%1,%2,%3};"
        : "+f"(c[0]), "+f"(c[1]), "+f"(c[2]), "+f"(c[3])
        : "r"(a[0]), "r"(a[1]), "r"(a[2]), "r"(a[3]),
          "r"(b[0]), "r"(b[1]));
}

__device__ __forceinline__ uint32_t pack_bf16x2(float lo, float hi) {
    __nv_bfloat162 h = __floats2bfloat162_rn(lo, hi);   // x=lo (low 16 bits)
    return *reinterpret_cast<uint32_t*>(&h);
}
__device__ __forceinline__ float bf_res(float f) {
    return f - __bfloat162float(__float2bfloat16(f));
}

// ---------------------------------------------------------------------------
// Prep: fp32 -> bf16 hi/lo split (row-major) for hidden states
// ---------------------------------------------------------------------------
__global__ void convert_split_kernel(const float* __restrict__ in,
                                     __nv_bfloat16* __restrict__ hi,
                                     __nv_bfloat16* __restrict__ lo, int n2)
{
    int i = blockIdx.x * blockDim.x + threadIdx.x;
    if (i >= n2) return;
    float2 v = ((const float2*)in)[i];
    __nv_bfloat16 h0 = __float2bfloat16(v.x);
    __nv_bfloat16 h1 = __float2bfloat16(v.y);
    __nv_bfloat162 hh; hh.x = h0; hh.y = h1;
    __nv_bfloat162 ll;
    ll.x = __float2bfloat16(v.x - __bfloat162float(h0));
    ll.y = __float2bfloat16(v.y - __bfloat162float(h1));
    ((__nv_bfloat162*)hi)[i] = hh;
    ((__nv_bfloat162*)lo)[i] = ll;
}

// in [R][C] fp32 -> out [C][R] bf16 hi/lo (for weights)
__global__ void transpose_split_kernel(const float* __restrict__ in,
                                       __nv_bfloat16* __restrict__ hi,
                                       __nv_bfloat16* __restrict__ lo,
                                       int R, int C)
{
    __shared__ float t[32][33];
    int c0 = blockIdx.x * 32, r0 = blockIdx.y * 32;
    int tx = threadIdx.x, ty = threadIdx.y;
    #pragma unroll
    for (int j = ty; j < 32; j += 8)
        t[j][tx] = in[(size_t)(r0 + j) * C + c0 + tx];
    __syncthreads();
    #pragma unroll
    for (int j = ty; j < 32; j += 8) {
        float v = t[tx][j];
        __nv_bfloat16 h = __float2bfloat16(v);
        size_t o = (size_t)(c0 + j) * R + r0 + tx;
        hi[o] = h;
        lo[o] = __float2bfloat16(v - __bfloat162float(h));
    }
}

// ---------------------------------------------------------------------------
// mma.sync bf16x3 GEMM: C[M,N] = A[M,K] @ B[N,K]^T (+bias), fp32 out
// Block 128x128, BK=32, 8 warps, 3-stage cp.async pipeline.
// ---------------------------------------------------------------------------
#define GSTAGE 40960
#define GEMM_SMEM (3 * GSTAGE)

__global__ __launch_bounds__(256, 1) void gemm_mma_bf16x3(
    const __nv_bfloat16* __restrict__ Ahi, const __nv_bfloat16* __restrict__ Alo,
    const __nv_bfloat16* __restrict__ Bhi, const __nv_bfloat16* __restrict__ Blo,
    const float* __restrict__ bias, float* __restrict__ C,
    int M, int N, int K)
{
    extern __shared__ char dsm[];
    const int tid  = threadIdx.x;
    const int lane = tid & 31, wid = tid >> 5;
    const int wm = wid & 3;
    const int wn = wid >> 2;
    const int g  = lane >> 2, t = lane & 3;
    const int m0 = blockIdx.y * 128, n0 = blockIdx.x * 128;

    const uint32_t sbase = smem_u32(dsm);

    float acc[2][8][4];
    #pragma unroll
    for (int mt = 0; mt < 2; mt++)
        #pragma unroll
        for (int nt = 0; nt < 8; nt++)
            #pragma unroll
            for (int j = 0; j < 4; j++) acc[mt][nt][j] = 0.0f;

    const int niter = K / 32;

    #define LOAD_STAGE(it) do {                                               \
        int _st = (it) % 3; int _kb = (it) * 32;                              \
        uint32_t _s0 = sbase + _st * GSTAGE;                                  \
        _Pragma("unroll")                                                     \
        for (int _c = tid; _c < 512; _c += 256) {                             \
            int _row = _c >> 2, _c8 = _c & 3;                                 \
            uint32_t _so = (uint32_t)(_row * 80 + _c8 * 16);                  \
            size_t _ga = (size_t)(m0 + _row) * K + _kb + _c8 * 8;             \
            size_t _gb = (size_t)(n0 + _row) * K + _kb + _c8 * 8;             \
            CP_ASYNC16(_s0 + _so,          Ahi + _ga);                        \
            CP_ASYNC16(_s0 + 10240 + _so,  Alo + _ga);                        \
            CP_ASYNC16(_s0 + 20480 + _so,  Bhi + _gb);                        \
            CP_ASYNC16(_s0 + 30720 + _so,  Blo + _gb);                        \
        }                                                                     \
        CP_COMMIT();                                                          \
    } while (0)

    LOAD_STAGE(0);
    LOAD_STAGE(1);

    for (int it = 0; it < niter; it++) {
        CP_WAIT(1);
        __syncthreads();
        if (it + 2 < niter) LOAD_STAGE(it + 2);
        else CP_COMMIT();   // keep group accounting uniform

        const uint32_t s0 = sbase + (it % 3) * GSTAGE;
        #pragma unroll
        for (int ks = 0; ks < 2; ks++) {
            const uint32_t koff = (uint32_t)(ks * 32 + t * 4);
            const uint32_t aB = s0 + (uint32_t)((wm * 32 + g) * 80) + koff;
            const uint32_t bB = s0 + 20480u + (uint32_t)((wn * 64 + g) * 80) + koff;

            uint32_t a[2][4], bhi[8][2], blo[8][2];

            #pragma unroll
            for (int mt = 0; mt < 2; mt++) {
                uint32_t ab = aB + (uint32_t)(mt * 16 * 80);
                a[mt][0] = lds_u32(ab);
                a[mt][1] = lds_u32(ab + 640);
                a[mt][2] = lds_u32(ab + 16);
                a[mt][3] = lds_u32(ab + 656);
            }
            #pragma unroll
            for (int nt = 0; nt < 8; nt++) {
                uint32_t bb = bB + (uint32_t)(nt * 8 * 80);
                bhi[nt][0] = lds_u32(bb);
                bhi[nt][1] = lds_u32(bb + 16);
            }
            #pragma unroll
            for (int mt = 0; mt < 2; mt++)
                #pragma unroll
                for (int nt = 0; nt < 8; nt++)
                    mma_bf16(acc[mt][nt], a[mt], bhi[nt]);

            #pragma unroll
            for (int nt = 0; nt < 8; nt++) {
                uint32_t bb = bB + 10240u + (uint32_t)(nt * 8 * 80);
                blo[nt][0] = lds_u32(bb);
                blo[nt][1] = lds_u32(bb + 16);
            }
            #pragma unroll
            for (int mt = 0; mt < 2; mt++)
                #pragma unroll
                for (int nt = 0; nt < 8; nt++)
                    mma_bf16(acc[mt][nt], a[mt], blo[nt]);

            #pragma unroll
            for (int mt = 0; mt < 2; mt++) {
                uint32_t ab = aB + 10240u + (uint32_t)(mt * 16 * 80);
                a[mt][0] = lds_u32(ab);
                a[mt][1] = lds_u32(ab + 640);
                a[mt][2] = lds_u32(ab + 16);
                a[mt][3] = lds_u32(ab + 656);
            }
            #pragma unroll
            for (int mt = 0; mt < 2; mt++)
                #pragma unroll
                for (int nt = 0; nt < 8; nt++)
                    mma_bf16(acc[mt][nt], a[mt], bhi[nt]);
        }
        __syncthreads();
    }

    const bool hasb = (bias != nullptr);
    #pragma unroll
    for (int mt = 0; mt < 2; mt++) {
        int row0 = m0 + wm * 32 + mt * 16 + g;
        #pragma unroll
        for (int nt = 0; nt < 8; nt++) {
            int col = n0 + wn * 64 + nt * 8 + t * 2;
            float bx = hasb ? bias[col] : 0.0f;
            float by = hasb ? bias[col + 1] : 0.0f;
            float2 v0, v1;
            v0.x = acc[mt][nt][0] + bx; v0.y = acc[mt][nt][1] + by;
            v1.x = acc[mt][nt][2] + bx; v1.y = acc[mt][nt][3] + by;
            *(float2*)(C + (size_t)row0 * N + col) = v0;
            *(float2*)(C + (size_t)(row0 + 8) * N + col) = v1;
        }
    }
    #undef LOAD_STAGE
}

// ---------------------------------------------------------------------------
// RoPE table
// ---------------------------------------------------------------------------
__global__ void rope_table_kernel(const int* __restrict__ positions)
{
    int idx = blockIdx.x * blockDim.x + threadIdx.x;
    if (idx >= T_TOK * (DH/2)) return;
    int t = idx >> 6;
    int i = idx & 63;
    double inv = pow(1.0e6, -(double)i / 64.0);
    double ang = (double)positions[t] * inv;
    g_rope_cos[idx] = (float)cos(ang);
    g_rope_sin[idx] = (float)sin(ang);
}

// ---------------------------------------------------------------------------
// Prep: rope + split Q (heads 0..27) and K (heads 28..31) from g_qkv
// Q -> [h][t][d], K -> [h][t][d], bf16 hi/lo
// ---------------------------------------------------------------------------
__global__ void ropesplit_qk_kernel(const float* __restrict__ qkv)
{
    int t = blockIdx.x;
    int head = blockIdx.y * blockDim.y + threadIdx.y;  // 0..31
    int i = threadIdx.x;                               // 0..63
    float c = g_rope_cos[t * 64 + i];
    float s = g_rope_sin[t * 64 + i];
    size_t src = (size_t)t * QKV_OUT + head * DH;
    float x1 = qkv[src + i];
    float x2 = qkv[src + 64 + i];
    float y1 = x1 * c - x2 * s;
    float y2 = x2 * c + x1 * s;
    __nv_bfloat16 h1 = __float2bfloat16(y1);
    __nv_bfloat16 h2 = __float2bfloat16(y2);
    if (head < HQ) {
        size_t base = ((size_t)head * T_TOK + t) * DH;
        g_Qhi[base + i]      = h1;
        g_Qlo[base + i]      = __float2bfloat16(y1 - __bfloat162float(h1));
        g_Qhi[base + 64 + i] = h2;
        g_Qlo[base + 64 + i] = __float2bfloat16(y2 - __bfloat162float(h2));
    } else {
        size_t base = ((size_t)(head - HQ) * T_TOK + t) * DH;
        g_Khi[base + i]      = h1;
        g_Klo[base + i]      = __float2bfloat16(y1 - __bfloat162float(h1));
        g_Khi[base + 64 + i] = h2;
        g_Klo[base + 64 + i] = __float2bfloat16(y2 - __bfloat162float(h2));
    }
}

// Prep: V transpose + split: g_qkv[t][4096 + dg] -> Vt[dg][t] (dg = kvh*128+d)
__global__ void vsplit_t_kernel(const float* __restrict__ qkv)
{
    __shared__ float tl[32][33];
    int t0 = blockIdx.x * 32, dg0 = blockIdx.y * 32;
    int tx = threadIdx.x, ty = threadIdx.y;
    #pragma unroll
    for (int j = ty; j < 32; j += 8)
        tl[j][tx] = qkv[(size_t)(t0 + j) * QKV_OUT + 4096 + dg0 + tx];
    __syncthreads();
    #pragma unroll
    for (int j = ty; j < 32; j += 8) {
        float v = tl[tx][j];   // qkv[t0+tx][4096+dg0+j]
        __nv_bfloat16 h = __float2bfloat16(v);
        size_t o = (size_t)(dg0 + j) * T_TOK + t0 + tx;
        g_Vthi[o] = h;
        g_Vtlo[o] = __float2bfloat16(v - __bfloat162float(h));
    }
}

// ---------------------------------------------------------------------------
// Tensor-core flash attention (bf16x3 on both GEMMs), causal, GQA.
// Block: 128 q-rows x 1 head. 8 warps, each owns 16 q-rows. KV block 64.
// Smem: Qhi/Qlo [128][136]b16, per stage: Khi/Klo [64][136], Vthi/Vtlo [128][72].
// ---------------------------------------------------------------------------
#define AQ_BYTES   34816                 // 128*272
#define ASTAGE     71680                 // 2*64*272 + 2*128*144
#define ATT_SMEM   (2*AQ_BYTES + 2*ASTAGE)   // 212992

__global__ __launch_bounds__(256, 1) void attn_mma_kernel(
    const __nv_bfloat16* __restrict__ Qhi, const __nv_bfloat16* __restrict__ Qlo,
    const __nv_bfloat16* __restrict__ Khi, const __nv_bfloat16* __restrict__ Klo,
    const __nv_bfloat16* __restrict__ Vthi, const __nv_bfloat16* __restrict__ Vtlo,
    __nv_bfloat16* __restrict__ Ohi, __nv_bfloat16* __restrict__ Olo)
{
    extern __shared__ char dsm[];
    const uint32_t sb = smem_u32(dsm);
    const uint32_t uQhi = sb, uQlo = sb + AQ_BYTES;
    const uint32_t stage0 = sb + 2 * AQ_BYTES;

    const int qb = blockIdx.x;
    const int h  = blockIdx.y;
    const int kvh = h / GQA_G;
    const int q0 = qb * 128;
    const int tid = threadIdx.x;
    const int w = tid >> 5, lane = tid & 31;
    const int g = lane >> 2, t = lane & 3;

    // --- async load Q (hi+lo): 128 rows x 16 chunks each ---
    for (int c = tid; c < 4096; c += 256) {
        int half = (c < 2048) ? 0 : 1;
        int j = c & 2047;
        int r = j >> 4, ch = j & 15;
        uint32_t sa = (half ? uQlo : uQhi) + (uint32_t)(r * 272 + ch * 16);
        const __nv_bfloat16* src = half ? Qlo : Qhi;
        CP_ASYNC16(sa, src + ((size_t)(h * T_TOK + q0 + r) * DH + ch * 8));
    }
    CP_COMMIT();

    const int nkb = 2 * qb + 2;

    #define LOADKV(kb_) do {                                                      \
        uint32_t _st = stage0 + ((kb_) & 1) * ASTAGE;                             \
        const int _kv0 = (kb_) * 64;                                              \
        for (int _c = tid; _c < 4096; _c += 256) {                                \
            if (_c < 2048) {                                                      \
                int _lo = (_c >= 1024); int _j = _c & 1023;                       \
                int _r = _j >> 4, _ch = _j & 15;                                  \
                uint32_t _sa = _st + (_lo ? 17408u : 0u)                          \
                             + (uint32_t)(_r * 272 + _ch * 16);                   \
                const __nv_bfloat16* _s = _lo ? Klo : Khi;                        \
                CP_ASYNC16(_sa, _s + ((size_t)(kvh * T_TOK + _kv0 + _r) * DH      \
                                      + _ch * 8));                                \
            } else {                                                              \
                int _i = _c - 2048;                                               \
                int _lo = (_i >= 1024); int _j = _i & 1023;                       \
                int _d = _j >> 3, _ch = _j & 7;                                   \
                uint32_t _sa = _st + 34816u + (_lo ? 18432u : 0u)                 \
                             + (uint32_t)(_d * 144 + _ch * 16);                   \
                const __nv_bfloat16* _s = _lo ? Vtlo : Vthi;                      \
                CP_ASYNC16(_sa, _s + ((size_t)(kvh * DH + _d) * T_TOK             \
                                      + _kv0 + _ch * 8));                         \
            }                                                                     \
        }                                                                         \
        CP_COMMIT();                                                              \
    } while (0)

    LOADKV(0);
    LOADKV(1);

    float o_[16][4];
    #pragma unroll
    for (int v = 0; v < 16; v++)
        #pragma unroll
        for (int j = 0; j < 4; j++) o_[v][j] = 0.0f;
    float m0 = -1e30f, m1 = -1e30f, l0 = 0.0f, l1 = 0.0f;

    const int qrow0 = q0 + w * 16 + g;
    const int qrow1 = qrow0 + 8;

    for (int kb = 0; kb < nkb; kb++) {
        CP_WAIT(1);
        __syncthreads();

        const uint32_t stK = stage0 + (kb & 1) * ASTAGE;
        const uint32_t stV = stK + 34816u;
        const bool skip = (kb == 2 * qb + 1) && (w < 4);

        if (!skip) {
            // ---- S = Q K^T (bf16x3) ----
            float s[8][4];
            #pragma unroll
            for (int j = 0; j < 8; j++)
                #pragma unroll
                for (int r = 0; r < 4; r++) s[j][r] = 0.0f;

            const uint32_t aQh0 = uQhi + (uint32_t)((w * 16 + g) * 272 + t * 4);
            const uint32_t aQl0 = uQlo + (uint32_t)((w * 16 + g) * 272 + t * 4);
            const uint32_t bK0  = stK + (uint32_t)(g * 272 + t * 4);

            #pragma unroll 1
            for (int kk = 0; kk < 8; kk++) {
                uint32_t aqh[4], aql[4];
                uint32_t qa = aQh0 + kk * 32;
                aqh[0] = lds_u32(qa);        aqh[1] = lds_u32(qa + 2176);
                aqh[2] = lds_u32(qa + 16);   aqh[3] = lds_u32(qa + 2192);
                uint32_t ql = aQl0 + kk * 32;
                aql[0] = lds_u32(ql);        aql[1] = lds_u32(ql + 2176);
                aql[2] = lds_u32(ql + 16);   aql[3] = lds_u32(ql + 2192);

                #pragma unroll
                for (int j = 0; j < 8; j++) {
                    uint32_t kb_off = bK0 + (uint32_t)(j * 8 * 272) + kk * 32;
                    uint32_t bkh[2], bkl[2];
                    bkh[0] = lds_u32(kb_off);
                    bkh[1] = lds_u32(kb_off + 16);
                    bkl[0] = lds_u32(kb_off + 17408);
                    bkl[1] = lds_u32(kb_off + 17424);
                    mma_bf16(s[j], aqh, bkh);
                    mma_bf16(s[j], aqh, bkl);
                    mma_bf16(s[j], aql, bkh);
                }
            }

            // ---- scale + causal mask ----
            const bool pmask = (kb >= 2 * qb);
            #pragma unroll
            for (int j = 0; j < 8; j++) {
                #pragma unroll
                for (int r = 0; r < 4; r++) {
                    float v = s[j][r] * SM_SCALE;
                    if (pmask) {
                        int col = kb * 64 + j * 8 + 2 * t + (r & 1);
                        int row = (r < 2) ? qrow0 : qrow1;
                        if (col > row) v = -1e9f;
                    }
                    s[j][r] = v;
                }
            }

            // ---- online softmax (rows g, g+8; reduce over quad t) ----
            float mx0 = -1e30f, mx1 = -1e30f;
            #pragma unroll
            for (int j = 0; j < 8; j++) {
                mx0 = fmaxf(mx0, fmaxf(s[j][0], s[j][1]));
                mx1 = fmaxf(mx1, fmaxf(s[j][2], s[j][3]));
            }
            mx0 = fmaxf(mx0, __shfl_xor_sync(0xffffffffu, mx0, 1));
            mx0 = fmaxf(mx0, __shfl_xor_sync(0xffffffffu, mx0, 2));
            mx1 = fmaxf(mx1, __shfl_xor_sync(0xffffffffu, mx1, 1));
            mx1 = fmaxf(mx1, __shfl_xor_sync(0xffffffffu, mx1, 2));

            float mn0 = fmaxf(m0, mx0), mn1 = fmaxf(m1, mx1);
            float a0 = __expf(m0 - mn0), a1 = __expf(m1 - mn1);
            m0 = mn0; m1 = mn1;

            float rs0 = 0.0f, rs1 = 0.0f;
            #pragma unroll
            for (int j = 0; j < 8; j++) {
                s[j][0] = __expf(s[j][0] - mn0);
                s[j][1] = __expf(s[j][1] - mn0);
                s[j][2] = __expf(s[j][2] - mn1);
                s[j][3] = __expf(s[j][3] - mn1);
                rs0 += s[j][0] + s[j][1];
                rs1 += s[j][2] + s[j][3];
            }
            rs0 += __shfl_xor_sync(0xffffffffu, rs0, 1);
            rs0 += __shfl_xor_sync(0xffffffffu, rs0, 2);
            rs1 += __shfl_xor_sync(0xffffffffu, rs1, 1);
            rs1 += __shfl_xor_sync(0xffffffffu, rs1, 2);
            l0 = l0 * a0 + rs0;
            l1 = l1 * a1 + rs1;

            #pragma unroll
            for (int v = 0; v < 16; v++) {
                o_[v][0] *= a0; o_[v][1] *= a0;
                o_[v][2] *= a1; o_[v][3] *= a1;
            }

            // ---- pack P into A-fragments (hi/lo) ----
            uint32_t aPhi[4][4], aPlo[4][4];
            #pragma unroll
            for (int u = 0; u < 4; u++) {
                aPhi[u][0] = pack_bf16x2(s[2*u][0],   s[2*u][1]);
                aPhi[u][1] = pack_bf16x2(s[2*u][2],   s[2*u][3]);
                aPhi[u][2] = pack_bf16x2(s[2*u+1][0], s[2*u+1][1]);
                aPhi[u][3] = pack_bf16x2(s[2*u+1][2], s[2*u+1][3]);
                aPlo[u][0] = pack_bf16x2(bf_res(s[2*u][0]),   bf_res(s[2*u][1]));
                aPlo[u][1] = pack_bf16x2(bf_res(s[2*u][2]),   bf_res(s[2*u][3]));
                aPlo[u][2] = pack_bf16x2(bf_res(s[2*u+1][0]), bf_res(s[2*u+1][1]));
                aPlo[u][3] = pack_bf16x2(bf_res(s[2*u+1][2]), bf_res(s[2*u+1][3]));
            }

            // ---- O += P V (bf16x3) ----
            const uint32_t bV0 = stV + (uint32_t)(g * 144 + t * 4);
            #pragma unroll
            for (int v = 0; v < 16; v++) {
                uint32_t vb = bV0 + (uint32_t)(v * 8 * 144);
                #pragma unroll
                for (int u = 0; u < 4; u++) {
                    uint32_t va = vb + u * 32;
                    uint32_t bh[2], bl[2];
                    bh[0] = lds_u32(va);
                    bh[1] = lds_u32(va + 16);
                    bl[0] = lds_u32(va + 18432);
                    bl[1] = lds_u32(va + 18448);
                    mma_bf16(o_[v], aPhi[u], bh);
                    mma_bf16(o_[v], aPhi[u], bl);
                    mma_bf16(o_[v], aPlo[u], bh);
                }
            }
        }

        __syncthreads();
        if (kb + 2 < nkb) LOADKV(kb + 2);
        else CP_COMMIT();
    }

    // ---- epilogue: normalize, split to bf16 hi/lo, write [t][h*128+d] ----
    float inv0 = 1.0f / l0, inv1 = 1.0f / l1;
    #pragma unroll
    for (int v = 0; v < 16; v++) {
        int d = v * 8 + 2 * t;
        float c0 = o_[v][0] * inv0, c1 = o_[v][1] * inv0;
        float c2 = o_[v][2] * inv1, c3 = o_[v][3] * inv1;
        size_t off0 = (size_t)qrow0 * ATTN_DIM + h * DH + d;
        size_t off1 = (size_t)qrow1 * ATTN_DIM + h * DH + d;
        *(uint32_t*)(Ohi + off0) = pack_bf16x2(c0, c1);
        *(uint32_t*)(Olo + off0) = pack_bf16x2(bf_res(c0), bf_res(c1));
        *(uint32_t*)(Ohi + off1) = pack_bf16x2(c2, c3);
        *(uint32_t*)(Olo + off1) = pack_bf16x2(bf_res(c2), bf_res(c3));
    }
    #undef LOADKV
}

// ---------------------------------------------------------------------------
// Launch
// ---------------------------------------------------------------------------
extern "C" void kernel_launch(void* const* d_in, const int* in_sizes, int n_in,
                              void* d_out, int out_size)
{
    const int*   positions = (const int*)  d_in[0];
    const float* hidden    = (const float*)d_in[1];
    const float* W_qkv     = (const float*)d_in[2];
    const float* b_qkv     = (const float*)d_in[3];
    const float* W_o       = (const float*)d_in[4];
    float* out = (float*)d_out;

    float* qkv;  cudaGetSymbolAddress((void**)&qkv, g_qkv);
    __nv_bfloat16 *Xhi, *Xlo, *Ahi, *Alo, *Wqh, *Wql, *Woh, *Wol;
    __nv_bfloat16 *Qhi, *Qlo, *Khi, *Klo, *Vthi, *Vtlo;
    cudaGetSymbolAddress((void**)&Xhi, g_X_hi);
    cudaGetSymbolAddress((void**)&Xlo, g_X_lo);
    cudaGetSymbolAddress((void**)&Ahi, g_A_hi);
    cudaGetSymbolAddress((void**)&Alo, g_A_lo);
    cudaGetSymbolAddress((void**)&Wqh, g_Wq_hi);
    cudaGetSymbolAddress((void**)&Wql, g_Wq_lo);
    cudaGetSymbolAddress((void**)&Woh, g_Wo_hi);
    cudaGetSymbolAddress((void**)&Wol, g_Wo_lo);
    cudaGetSymbolAddress((void**)&Qhi, g_Qhi);
    cudaGetSymbolAddress((void**)&Qlo, g_Qlo);
    cudaGetSymbolAddress((void**)&Khi, g_Khi);
    cudaGetSymbolAddress((void**)&Klo, g_Klo);
    cudaGetSymbolAddress((void**)&Vthi, g_Vthi);
    cudaGetSymbolAddress((void**)&Vtlo, g_Vtlo);

    cudaFuncSetAttribute(gemm_mma_bf16x3,
                         cudaFuncAttributeMaxDynamicSharedMemorySize, GEMM_SMEM);
    cudaFuncSetAttribute(attn_mma_kernel,
                         cudaFuncAttributeMaxDynamicSharedMemorySize, ATT_SMEM);

    // 0) rope table + hidden/weight splits
    {
        int n = T_TOK * (DH / 2);
        rope_table_kernel<<<(n + 255) / 256, 256>>>(positions);
        int n2 = T_TOK * D_MODEL / 2;
        convert_split_kernel<<<(n2 + 255)/256, 256>>>(hidden, Xhi, Xlo, n2);
        dim3 b1(32, 8);
        dim3 g1(QKV_OUT/32, D_MODEL/32);
        transpose_split_kernel<<<g1, b1>>>(W_qkv, Wqh, Wql, D_MODEL, QKV_OUT);
        dim3 g2(D_MODEL/32, ATTN_DIM/32);
        transpose_split_kernel<<<g2, b1>>>(W_o, Woh, Wol, ATTN_DIM, D_MODEL);
    }

    // 1) QKV projection
    {
        dim3 grid(QKV_OUT / 128, T_TOK / 128);
        gemm_mma_bf16x3<<<grid, 256, GEMM_SMEM>>>(
            Xhi, Xlo, Wqh, Wql, b_qkv, qkv, T_TOK, QKV_OUT, D_MODEL);
    }

    // 2) rope+split Q/K, transpose+split V
    {
        dim3 grid(T_TOK, 8), block(64, 4);
        ropesplit_qk_kernel<<<grid, block>>>(qkv);
        dim3 gv(T_TOK/32, (HKV*DH)/32), bv(32, 8);
        vsplit_t_kernel<<<gv, bv>>>(qkv);
    }

    // 3) tensor-core flash attention -> writes bf16 hi/lo directly
    {
        dim3 grid(T_TOK / 128, HQ);
        attn_mma_kernel<<<grid, 256, ATT_SMEM>>>(
            Qhi, Qlo, Khi, Klo, Vthi, Vtlo, Ahi, Alo);
    }

    // 4) O projection
    {
        dim3 grid(D_MODEL / 128, T_TOK / 128);
        gemm_mma_bf16x3<<<grid, 256, GEMM_SMEM>>>(
            Ahi, Alo, Woh, Wol, nullptr, out, T_TOK, D_MODEL, ATTN_DIM);
    }
}